// round 12
// baseline (speedup 1.0000x reference)
#include <cuda_runtime.h>
#include <math.h>

#define BB 4
#define NA 50
#define SZ 256
#define SS (SZ*SZ)
#define NC 32
#define PP 512
#define CEN 127.5f
#define NZ 8

typedef unsigned long long u64;

// ---- packed f32x2 helpers (sm_103a dual-rate fp32 path) ----
__device__ __forceinline__ u64 pk2(float lo, float hi) {
    u64 r; asm("mov.b64 %0, {%1, %2};" : "=l"(r) : "f"(lo), "f"(hi)); return r;
}
__device__ __forceinline__ u64 fma2(u64 a, u64 b, u64 c) {
    u64 d; asm("fma.rn.f32x2 %0, %1, %2, %3;" : "=l"(d) : "l"(a), "l"(b), "l"(c)); return d;
}
__device__ __forceinline__ void unpk2(u64 v, float& lo, float& hi) {
    asm("mov.b64 {%0, %1}, %2;" : "=f"(lo), "=f"(hi) : "l"(v));
}

// ---------------- scratch ----------------
__device__ float g_part[NZ*BB*NA*SZ];
__device__ float g_filt[BB*NA*SZ];
__device__ float g_h1[BB*NC*SS];
__device__ float g_h2[BB*NC*SS];
__device__ float g_up[BB*SS];
__device__ __align__(16) u64 g_U[16*32*16];   // Winograd U: [c][ic][ocp] packed oc-pairs

// ---------------- 1. radon forward: band-tiled, mask fused ----------------
__global__ void __launch_bounds__(256) k_radon(const float* __restrict__ yprev,
                                               const float* __restrict__ angles) {
    __shared__ float s_band[33][257];
    int a = blockIdx.x, b = blockIdx.y, z = blockIdx.z;
    int s = threadIdx.x;
    int y0 = z * 32;
    int lo = (z == 0) ? -1 : y0;
    int hi = y0 + 32;

    const float* im = &yprev[b * SS];
    float dxm = (float)s - CEN;
    #pragma unroll
    for (int i = 0; i < 33; ++i) {
        int gy = y0 + i;
        float dym = (float)gy - CEN;
        float m = (dym * dym + dxm * dxm <= 16384.0f) ? 1.0f : 0.0f;
        s_band[i][s] = (gy <= 255) ? im[gy * SZ + s] * m : 0.0f;
    }
    __syncthreads();

    float ca, sa;
    __sincosf(angles[a], &sa, &ca);
    float sf = (float)s - CEN;
    float rowA = sf * sa - CEN * ca + CEN;
    float colA = sf * ca + CEN * sa + CEN;

    float tmin, tmax;
    if (fabsf(ca) > 1e-6f) {
        float t1 = ((float)lo - 0.5f - rowA) / ca;
        float t2 = ((float)hi + 0.5f - rowA) / ca;
        tmin = fminf(t1, t2) - 1.0f;
        tmax = fmaxf(t1, t2) + 1.0f;
    } else {
        bool inb = (rowA >= (float)lo - 1.0f) && (rowA < (float)hi + 1.0f);
        tmin = inb ? 0.0f : 1.0f;
        tmax = inb ? 255.0f : 0.0f;
    }
    int ts = max(0, (int)floorf(tmin));
    int te = min(255, (int)ceilf(tmax));

    float sum = 0.0f;
    for (int t = ts; t <= te; ++t) {
        float row = rowA + (float)t * ca;
        float rf = floorf(row);
        int r0 = (int)rf;
        if (r0 < lo || r0 >= hi) continue;
        float wr = row - rf;
        float col = colA - (float)t * sa;
        float cf = floorf(col);
        int c0 = (int)cf;
        float wc = col - cf;
        int c0c = min(max(c0, 0), 255);
        int c1c = min(max(c0 + 1, 0), 255);
        float mc0 = (c0 == c0c) ? 1.0f : 0.0f;
        float mc1 = (c0 + 1 == c1c) ? 1.0f : 0.0f;
        float mr0 = (r0 >= 0) ? 1.0f : 0.0f;
        int lr = r0 - y0;
        int lrc = max(lr, 0);
        float v00 = s_band[lrc][c0c],     v01 = s_band[lrc][c1c];
        float v10 = s_band[lr + 1][c0c],  v11 = s_band[lr + 1][c1c];
        float top = mc0 * (1.0f - wc) * v00 + mc1 * wc * v01;
        float bot = mc0 * (1.0f - wc) * v10 + mc1 * wc * v11;
        sum += mr0 * (1.0f - wr) * top + wr * bot;
    }
    g_part[((z * BB + b) * NA + a) * SZ + s] = sum;
}

// ---------------- 2. ramp filter ----------------
__device__ __forceinline__ float hval(int m) {
    if (m == 0) return 0.5f;
    if ((m & 1) == 0) return 0.0f;
    float sv = sinf((float)M_PI * (float)m / (float)PP);
    return -2.0f / ((float)PP * (float)PP * sv * sv);
}
__global__ void k_filter(const float* __restrict__ x_sino) {
    __shared__ float sd[SZ];
    __shared__ float sh[PP];
    int a = blockIdx.x, b = blockIdx.y;
    int n = threadIdx.x;
    int base = (b * NA + a) * SZ + n;
    float d = -x_sino[base];
    #pragma unroll
    for (int z = 0; z < NZ; ++z) d += g_part[((z * BB + b) * NA + a) * SZ + n];
    sd[n] = d;
    sh[n] = hval(n);
    sh[n + 256] = hval(n + 256);
    __syncthreads();
    float acc = 0.5f * sd[n];
    int m0 = (n & 1) ^ 1;
    #pragma unroll 8
    for (int j = 0; j < 128; ++j) {
        int m = m0 + 2 * j;
        acc += sd[m] * sh[(n - m + PP) & (PP - 1)];
    }
    g_filt[base] = acc * (float)(M_PI / (2.0 * NA));
}

// ---------------- 3. backprojection + update (4 rows/block) ----------------
__global__ void __launch_bounds__(1024) k_backproj(const float* __restrict__ yprev,
                                                   const float* __restrict__ angles,
                                                   const float* __restrict__ step,
                                                   float* __restrict__ out_up) {
    __shared__ float s_sino[25 * SZ];
    __shared__ float s_cos[NA], s_sin[NA];
    int b = blockIdx.y;
    int tid = threadIdx.x;
    int j = tid & 255, quart = tid >> 8;
    int i = blockIdx.x * 4 + quart;
    if (tid < NA) { s_cos[tid] = cosf(angles[tid]); s_sin[tid] = sinf(angles[tid]); }
    __syncthreads();
    float xx = (float)j - CEN, yy = (float)i - CEN;
    float acc = 0.0f;
    for (int ch = 0; ch < 2; ++ch) {
        for (int k = tid; k < 25 * SZ; k += 1024) {
            s_sino[k] = g_filt[(b * NA + ch * 25) * SZ + k];
        }
        __syncthreads();
        #pragma unroll 5
        for (int al = 0; al < 25; ++al) {
            int a = ch * 25 + al;
            float det = xx * s_cos[a] + yy * s_sin[a] + CEN;
            float df = floorf(det);
            int i0 = (int)df;
            i0 = i0 < 0 ? 0 : (i0 > SZ - 2 ? SZ - 2 : i0);
            float w = det - (float)i0;
            float v = s_sino[al * SZ + i0] * (1.0f - w) + s_sino[al * SZ + i0 + 1] * w;
            if (det >= 0.0f && det <= (float)(SZ - 1)) acc += v;
        }
        __syncthreads();
    }
    float m = (xx*xx + yy*yy <= 16384.0f) ? 1.0f : 0.0f;
    int o = b * SS + i * SZ + j;
    out_up[o] = yprev[o] + step[0] * (acc * m);
}

// ---------------- 4. conv1: 2 -> 32 tiled f32x2 (proven) -------------------
#define RW 36
__global__ void __launch_bounds__(256) k_conv1(const float* __restrict__ yup,
                                               const float* __restrict__ ycat,
                                               const float* __restrict__ w1,
                                               const float* __restrict__ b1) {
    __shared__ __align__(16) float s_w2[18 * 32];
    __shared__ float s_b[NC];
    __shared__ __align__(16) float s_in0[10 * RW];
    __shared__ __align__(16) float s_in1[10 * RW];
    int tid = threadIdx.x;
    int b = blockIdx.z;
    int gx0 = blockIdx.x * 32 - 1;
    int gy0 = blockIdx.y * 8 - 1;
    for (int idx = tid; idx < 18 * 32; idx += 256) {
        int kk = idx >> 5, oc = idx & 31;
        s_w2[idx] = w1[oc * 18 + kk];
    }
    if (tid < NC) s_b[tid] = b1[tid];
    for (int idx = tid; idx < 10 * RW; idx += 256) {
        int rr = idx / RW, ccx = idx % RW;
        int gy = gy0 + rr, gx = gx0 + ccx;
        bool ok = (ccx < 34) && (gy >= 0) && (gy < SZ) && (gx >= 0) && (gx < SZ);
        int gi = b * SS + gy * SZ + gx;
        s_in0[idx] = ok ? yup[gi]  : 0.0f;
        s_in1[idx] = ok ? ycat[gi] : 0.0f;
    }
    __syncthreads();

    int q = tid & 7, r = (tid >> 3) & 7, og = tid >> 6;
    u64 acc2[4][4];
    #pragma unroll
    for (int op = 0; op < 4; ++op) {
        int oc0 = og * 8 + 2 * op;
        u64 bp = pk2(s_b[oc0], s_b[oc0 + 1]);
        #pragma unroll
        for (int p = 0; p < 4; ++p) acc2[op][p] = bp;
    }
    #pragma unroll
    for (int ic = 0; ic < 2; ++ic) {
        const float* inb = ic ? s_in1 : s_in0;
        const float* wb  = &s_w2[ic * 288];
        #pragma unroll
        for (int ky = 0; ky < 3; ++ky) {
            const float* rowp = inb + (r + ky) * RW + q * 4;
            float4 va = *(const float4*)rowp;
            float2 vb = *(const float2*)(rowp + 4);
            float ivf[6] = {va.x, va.y, va.z, va.w, vb.x, vb.y};
            u64 ivp[6];
            #pragma unroll
            for (int m = 0; m < 6; ++m) ivp[m] = pk2(ivf[m], ivf[m]);
            #pragma unroll
            for (int kx = 0; kx < 3; ++kx) {
                const ulonglong2 wv0 = *(const ulonglong2*)&wb[(ky*3+kx)*32 + og*8];
                const ulonglong2 wv1 = *(const ulonglong2*)&wb[(ky*3+kx)*32 + og*8 + 4];
                u64 wp[4] = {wv0.x, wv0.y, wv1.x, wv1.y};
                #pragma unroll
                for (int op = 0; op < 4; ++op)
                    #pragma unroll
                    for (int p = 0; p < 4; ++p)
                        acc2[op][p] = fma2(wp[op], ivp[kx + p], acc2[op][p]);
            }
        }
    }
    int gy = blockIdx.y * 8 + r;
    int gxb = blockIdx.x * 32 + q * 4;
    #pragma unroll
    for (int op = 0; op < 4; ++op) {
        int oc0 = og * 8 + 2 * op;
        float l0,h0,l1,h1,l2,h2,l3,h3;
        unpk2(acc2[op][0], l0, h0); unpk2(acc2[op][1], l1, h1);
        unpk2(acc2[op][2], l2, h2); unpk2(acc2[op][3], l3, h3);
        float4 vlo = make_float4(fmaxf(l0,0.f), fmaxf(l1,0.f), fmaxf(l2,0.f), fmaxf(l3,0.f));
        float4 vhi = make_float4(fmaxf(h0,0.f), fmaxf(h1,0.f), fmaxf(h2,0.f), fmaxf(h3,0.f));
        *(float4*)&g_h1[((b * NC + oc0)     << 16) + gy * SZ + gxb] = vlo;
        *(float4*)&g_h1[((b * NC + oc0 + 1) << 16) + gy * SZ + gxb] = vhi;
    }
}

// ---------------- 5a. Winograd U prep: U = G g G^T, packed oc-pairs --------
__global__ void k_prepw(const float* __restrict__ w2) {
    int tid = threadIdx.x;
    for (int it = tid; it < 512; it += 256) {
        int ic = it >> 4, ocp = it & 15;
        float U2[2][16];
        #pragma unroll
        for (int s = 0; s < 2; ++s) {
            int oc = ocp * 2 + s;
            float g[9];
            #pragma unroll
            for (int k = 0; k < 9; ++k) g[k] = w2[oc * 288 + ic * 9 + k];
            float t[4][3];
            #pragma unroll
            for (int l = 0; l < 3; ++l) {
                t[0][l] = g[l];
                t[1][l] = 0.5f * (g[l] + g[3 + l] + g[6 + l]);
                t[2][l] = 0.5f * (g[l] - g[3 + l] + g[6 + l]);
                t[3][l] = g[6 + l];
            }
            #pragma unroll
            for (int i = 0; i < 4; ++i) {
                U2[s][i*4+0] = t[i][0];
                U2[s][i*4+1] = 0.5f * (t[i][0] + t[i][1] + t[i][2]);
                U2[s][i*4+2] = 0.5f * (t[i][0] - t[i][1] + t[i][2]);
                U2[s][i*4+3] = t[i][2];
            }
        }
        #pragma unroll
        for (int c = 0; c < 16; ++c)
            g_U[(c * 32 + ic) * 16 + ocp] = pk2(U2[0][c], U2[1][c]);
    }
}

// ---------------- 5b. conv2: Winograd F(2x2,3x3), f32x2 GEMM ---------------
// grid (8, 16, BB), 256 thr. CTA region 32x16 px = 16x8 output tiles.
// thread = 1 tile x 8 oc-pairs (half selects oc 0-15 / 16-31).
#define CV2W_SMEM (65536 + 41472)
__global__ void __launch_bounds__(256, 2) k_conv2w(const float* __restrict__ b2) {
    extern __shared__ __align__(16) unsigned char sm[];
    u64*   s_U  = (u64*)sm;                 // [16c][32ic][16ocp]
    float* s_in = (float*)(sm + 65536);     // [16ic][18][36]
    __shared__ float s_b[NC];
    int tid = threadIdx.x;
    int b = blockIdx.z, bx = blockIdx.x, by = blockIdx.y;
    int tile = tid & 127, half = tid >> 7;
    int tx = tile & 15, ty = tile >> 4;

    if (tid < NC) s_b[tid] = b2[tid];
    {   // copy all U to smem (64 KB)
        const uint4* src = (const uint4*)g_U;
        uint4* dst = (uint4*)sm;
        for (int i = tid; i < 4096; i += 256) dst[i] = src[i];
    }

    // B^T row/col combo tables: combo_i(X) = SA[i]*X[KA[i]] + SB[i]*X[KB[i]]
    const int   KA[4] = {0,1,1,1},  KB[4] = {2,2,2,3};
    const float SA[4] = {1,1,-1,1}, SB[4] = {-1,1,1,-1};
    const float AT0[4] = {1,1,1,0}, AT1[4] = {0,1,-1,-1};

    u64 O[8][4];
    #pragma unroll
    for (int o = 0; o < 8; ++o)
        #pragma unroll
        for (int p = 0; p < 4; ++p) O[o][p] = 0ULL;

    int base_t = (2 * ty) * 36 + 2 * tx;

    for (int icc = 0; icc < 2; ++icc) {
        __syncthreads();
        for (int idx = tid; idx < 16 * 18 * 36; idx += 256) {
            int ic = idx / 648, rem = idx % 648;
            int r = rem / 36, cc = rem % 36;
            int gy = by * 16 - 1 + r, gx = bx * 32 - 1 + cc;
            bool ok = (cc < 34) && (gy >= 0) && (gy < SZ) && (gx >= 0) && (gx < SZ);
            s_in[idx] = ok ? g_h1[((b * NC + icc * 16 + ic) << 16) + gy * SZ + gx] : 0.0f;
        }
        __syncthreads();

        #pragma unroll
        for (int c = 0; c < 16; ++c) {
            const int i = c >> 2, j = c & 3;
            u64 M[8];
            #pragma unroll
            for (int o = 0; o < 8; ++o) M[o] = 0ULL;
            #pragma unroll 4
            for (int ic = 0; ic < 16; ++ic) {
                const float* dbase = s_in + ic * 648 + base_t;
                const float* ra = dbase + KA[i] * 36;
                const float* rb = dbase + KB[i] * 36;
                float xa = SA[j] * ra[KA[j]] + SB[j] * ra[KB[j]];   // col combo on row KA[i]
                float xb = SA[j] * rb[KA[j]] + SB[j] * rb[KB[j]];   // col combo on row KB[i]
                float v = SA[i] * xa + SB[i] * xb;
                u64 vv = pk2(v, v);
                const u64* up = s_U + (((c * 32 + icc * 16 + ic) << 4) + half * 8);
                const ulonglong2 w0 = *(const ulonglong2*)(up);
                const ulonglong2 w1 = *(const ulonglong2*)(up + 2);
                const ulonglong2 w2v = *(const ulonglong2*)(up + 4);
                const ulonglong2 w3 = *(const ulonglong2*)(up + 6);
                M[0] = fma2(vv, w0.x, M[0]);  M[1] = fma2(vv, w0.y, M[1]);
                M[2] = fma2(vv, w1.x, M[2]);  M[3] = fma2(vv, w1.y, M[3]);
                M[4] = fma2(vv, w2v.x, M[4]); M[5] = fma2(vv, w2v.y, M[5]);
                M[6] = fma2(vv, w3.x, M[6]);  M[7] = fma2(vv, w3.y, M[7]);
            }
            #pragma unroll
            for (int dy = 0; dy < 2; ++dy) {
                const float au = (dy == 0) ? AT0[i] : AT1[i];
                if (au == 0.0f) continue;
                #pragma unroll
                for (int dx = 0; dx < 2; ++dx) {
                    const float av = (dx == 0) ? AT0[j] : AT1[j];
                    if (av == 0.0f) continue;
                    const float sgn = au * av;          // ±1, compile-time
                    const u64 sp = pk2(sgn, sgn);
                    const int p = dy * 2 + dx;
                    #pragma unroll
                    for (int o = 0; o < 8; ++o) O[o][p] = fma2(M[o], sp, O[o][p]);
                }
            }
        }
    }

    int ybase = by * 16 + 2 * ty, xbase = bx * 32 + 2 * tx;
    #pragma unroll
    for (int o = 0; o < 8; ++o) {
        int oc0 = (half * 8 + o) * 2;
        float b0 = s_b[oc0], b1 = s_b[oc0 + 1];
        #pragma unroll
        for (int dy = 0; dy < 2; ++dy)
            #pragma unroll
            for (int dx = 0; dx < 2; ++dx) {
                float lo, hi; unpk2(O[o][dy * 2 + dx], lo, hi);
                int off = (ybase + dy) * SZ + xbase + dx;
                g_h2[((b * NC + oc0)     << 16) + off] = fmaxf(lo + b0, 0.0f);
                g_h2[((b * NC + oc0 + 1) << 16) + off] = fmaxf(hi + b1, 0.0f);
            }
    }
}

// ---------------- 6. conv3: 32 -> 1, smem-chunked (proven) -----------------
__global__ void __launch_bounds__(256) k_conv3(const float* __restrict__ w3,
                                               const float* __restrict__ b3,
                                               float* __restrict__ out_img) {
    __shared__ float s_w[NC * 9];
    __shared__ __align__(16) float s_in[8 * 10 * RW];
    int tid = threadIdx.x;
    int b = blockIdx.z;
    int gx0 = blockIdx.x * 32 - 1;
    int gy0 = blockIdx.y * 8 - 1;
    for (int k = tid; k < NC * 9; k += 256) s_w[k] = w3[k];

    int jl = tid & 31, il = tid >> 5;
    float acc = b3[0];
    for (int cc = 0; cc < 4; ++cc) {
        __syncthreads();
        for (int idx = tid; idx < 8 * 10 * RW; idx += 256) {
            int ic = idx / (10 * RW), rem = idx % (10 * RW);
            int rr = rem / RW, ccx = rem % RW;
            int gy = gy0 + rr, gx = gx0 + ccx;
            bool ok = (ccx < 34) && (gy >= 0) && (gy < SZ) && (gx >= 0) && (gx < SZ);
            s_in[idx] = ok ? g_h2[((b * NC + cc * 8 + ic) << 16) + gy * SZ + gx] : 0.0f;
        }
        __syncthreads();
        #pragma unroll
        for (int ic = 0; ic < 8; ++ic) {
            const float* inb = &s_in[ic * 10 * RW];
            const float* w = &s_w[(cc * 8 + ic) * 9];
            #pragma unroll
            for (int ky = 0; ky < 3; ++ky) {
                const float* rowp = inb + (il + ky) * RW + jl;
                acc += rowp[0] * w[ky*3] + rowp[1] * w[ky*3+1] + rowp[2] * w[ky*3+2];
            }
        }
    }
    int gy = blockIdx.y * 8 + il;
    int gx = blockIdx.x * 32 + jl;
    out_img[b * SS + gy * SZ + gx] = acc;
}

// ---------------- launch ----------------
extern "C" void kernel_launch(void* const* d_in, const int* in_sizes, int n_in,
                              void* d_out, int out_size) {
    const float *x_sino = 0, *y_prev = 0, *y_cat = 0, *angles = 0, *step = 0;
    const float *w1 = 0, *b1 = 0, *w2 = 0, *b2 = 0, *w3 = 0, *b3 = 0;

    int ix = -1;
    for (int i = 0; i < n_in; ++i) if (in_sizes[i] == 51200) ix = i;
    bool dict_order = (ix == 0);

    int n262 = 0, n32 = 0, n1 = 0;
    for (int i = 0; i < n_in; ++i) {
        const float* p = (const float*)d_in[i];
        switch (in_sizes[i]) {
            case 51200: x_sino = p; break;
            case 50:    angles = p; break;
            case 576:   w1 = p; break;
            case 9216:  w2 = p; break;
            case 288:   w3 = p; break;
            case 262144:
                if (dict_order) { if (n262 == 0) y_prev = p; else y_cat = p; }
                else            { if (n262 == 0) y_cat  = p; else y_prev = p; }
                ++n262; break;
            case 32:
                if (n32 == 0) b1 = p; else b2 = p;
                ++n32; break;
            case 1:
                if (dict_order) { if (n1 == 0) step = p; else b3 = p; }
                else            { if (n1 == 0) b3   = p; else step = p; }
                ++n1; break;
            default: break;
        }
    }

    float* out_img = (float*)d_out;
    float* out_up;
    if (out_size >= 2 * BB * SS) {
        out_up = (float*)d_out + BB * SS;
    } else {
        cudaGetSymbolAddress((void**)&out_up, g_up);
    }

    cudaFuncSetAttribute(k_conv2w, cudaFuncAttributeMaxDynamicSharedMemorySize, CV2W_SMEM);

    k_prepw<<<1, 256>>>(w2);
    k_radon<<<dim3(NA, BB, NZ), 256>>>(y_prev, angles);
    k_filter<<<dim3(NA, BB), 256>>>(x_sino);
    k_backproj<<<dim3(SZ / 4, BB), 1024>>>(y_prev, angles, step, out_up);
    k_conv1<<<dim3(8, 32, BB), 256>>>(out_up, y_cat, w1, b1);
    k_conv2w<<<dim3(8, 16, BB), 256, CV2W_SMEM>>>(b2);
    k_conv3<<<dim3(8, 32, BB), 256>>>(w3, b3, out_img);
}

// round 13
// speedup vs baseline: 1.2139x; 1.2139x over previous
#include <cuda_runtime.h>
#include <math.h>

#define BB 4
#define NA 50
#define SZ 256
#define SS (SZ*SZ)
#define NC 32
#define PP 512
#define CEN 127.5f
#define NZ 8
#define BW 262   // padded band width: 3 | 256 | 3

typedef unsigned long long u64;

// ---- packed f32x2 helpers (sm_103a dual-rate fp32 path) ----
__device__ __forceinline__ u64 pk2(float lo, float hi) {
    u64 r; asm("mov.b64 %0, {%1, %2};" : "=l"(r) : "f"(lo), "f"(hi)); return r;
}
__device__ __forceinline__ u64 fma2(u64 a, u64 b, u64 c) {
    u64 d; asm("fma.rn.f32x2 %0, %1, %2, %3;" : "=l"(d) : "l"(a), "l"(b), "l"(c)); return d;
}
__device__ __forceinline__ void unpk2(u64 v, float& lo, float& hi) {
    asm("mov.b64 {%0, %1}, %2;" : "=f"(lo), "=f"(hi) : "l"(v));
}

// ---------------- scratch ----------------
__device__ float g_part[NZ*BB*NA*SZ];
__device__ float g_filt[BB*NA*SZ];
__device__ float g_h1[BB*NC*SS];
__device__ float g_h2[BB*NC*SS];
__device__ float g_up[BB*SS];

// ---------------- 1. radon forward: padded band, exact interval ------------
__global__ void __launch_bounds__(256) k_radon(const float* __restrict__ yprev,
                                               const float* __restrict__ angles) {
    __shared__ float s_band[34][BW];
    int a = blockIdx.x, b = blockIdx.y, z = blockIdx.z;
    int s = threadIdx.x;
    int y0 = z * 32;
    float lof = (z == 0) ? -1.0f : (float)y0;
    float hif = (float)(y0 + 32);

    // load rows gy = y0-1 .. y0+32 with circle mask; halo rows are zero
    const float* im = &yprev[b * SS];
    float dxm = (float)s - CEN;
    #pragma unroll
    for (int i = 0; i < 34; ++i) {
        int gy = y0 - 1 + i;
        float dym = (float)gy - CEN;
        float m = (dym * dym + dxm * dxm <= 16384.0f) ? 1.0f : 0.0f;
        s_band[i][s + 3] = (gy >= 0 && gy <= 255) ? im[gy * SZ + s] * m : 0.0f;
    }
    if (s < 34) {   // zero the 3 pad columns on each side
        s_band[s][0] = 0.0f; s_band[s][1] = 0.0f; s_band[s][2] = 0.0f;
        s_band[s][259] = 0.0f; s_band[s][260] = 0.0f; s_band[s][261] = 0.0f;
    }
    __syncthreads();

    float ca, sa;
    __sincosf(angles[a], &sa, &ca);
    float sf = (float)s - CEN;
    float rowA = sf * sa - CEN * ca + CEN;   // row(t) = rowA + t*ca
    float colA = sf * ca + CEN * sa + CEN;   // col(t) = colA - t*sa

    // exact-enough t interval (ownership test below guarantees exactness)
    float tl = 0.0f, th = 255.0f;
    if (fabsf(ca) > 1e-7f) {
        float b1 = (lof - rowA) / ca, b2 = (hif - rowA) / ca;
        tl = fmaxf(tl, fminf(b1, b2) - 1.0f);
        th = fminf(th, fmaxf(b1, b2) + 1.0f);
    } else if (!(rowA >= lof - 0.5f && rowA < hif + 0.5f)) {
        tl = 1.0f; th = 0.0f;
    }
    if (fabsf(sa) > 1e-7f) {
        float b1 = (colA + 1.6f) / sa, b2 = (colA - 256.6f) / sa;
        tl = fmaxf(tl, fminf(b1, b2) - 1.0f);
        th = fminf(th, fmaxf(b1, b2) + 1.0f);
    } else if (!(colA >= -1.6f && colA <= 256.6f)) {
        tl = 1.0f; th = 0.0f;
    }
    int ts = max(0, (int)floorf(tl));
    int te = min(255, (int)ceilf(th));

    float sum = 0.0f;
    for (int t = ts; t <= te; ++t) {
        float tf = (float)t;
        float row = rowA + tf * ca;
        if (row < lof || row >= hif) continue;   // exact band ownership
        float col = colA - tf * sa;
        float rf = floorf(row), cf = floorf(col);
        float wr = row - rf, wc = col - cf;
        int lr = (int)rf - (y0 - 1);             // 0..32 guaranteed
        int ci = min(max((int)cf + 3, 0), 260);  // pads are zero: clamp = exact
        const float* r0p = &s_band[lr][ci];
        const float* r1p = &s_band[lr + 1][ci];
        float v00 = r0p[0], v01 = r0p[1];
        float v10 = r1p[0], v11 = r1p[1];
        float top = v00 + wc * (v01 - v00);
        float bot = v10 + wc * (v11 - v10);
        sum += top + wr * (bot - top);
    }
    g_part[((z * BB + b) * NA + a) * SZ + s] = sum;
}

// ---------------- 2. ramp filter ----------------
__device__ __forceinline__ float hval(int m) {
    if (m == 0) return 0.5f;
    if ((m & 1) == 0) return 0.0f;
    float sv = sinf((float)M_PI * (float)m / (float)PP);
    return -2.0f / ((float)PP * (float)PP * sv * sv);
}
__global__ void k_filter(const float* __restrict__ x_sino) {
    __shared__ float sd[SZ];
    __shared__ float sh[PP];
    int a = blockIdx.x, b = blockIdx.y;
    int n = threadIdx.x;
    int base = (b * NA + a) * SZ + n;
    float d = -x_sino[base];
    #pragma unroll
    for (int z = 0; z < NZ; ++z) d += g_part[((z * BB + b) * NA + a) * SZ + n];
    sd[n] = d;
    sh[n] = hval(n);
    sh[n + 256] = hval(n + 256);
    __syncthreads();
    float acc = 0.5f * sd[n];
    int m0 = (n & 1) ^ 1;
    #pragma unroll 8
    for (int j = 0; j < 128; ++j) {
        int m = m0 + 2 * j;
        acc += sd[m] * sh[(n - m + PP) & (PP - 1)];
    }
    g_filt[base] = acc * (float)(M_PI / (2.0 * NA));
}

// ---------------- 3. backprojection + update (4 rows/block) ----------------
__global__ void __launch_bounds__(1024) k_backproj(const float* __restrict__ yprev,
                                                   const float* __restrict__ angles,
                                                   const float* __restrict__ step,
                                                   float* __restrict__ out_up) {
    __shared__ float s_sino[25 * SZ];
    __shared__ float s_cos[NA], s_sin[NA];
    int b = blockIdx.y;
    int tid = threadIdx.x;
    int j = tid & 255, quart = tid >> 8;
    int i = blockIdx.x * 4 + quart;
    if (tid < NA) { s_cos[tid] = cosf(angles[tid]); s_sin[tid] = sinf(angles[tid]); }
    __syncthreads();
    float xx = (float)j - CEN, yy = (float)i - CEN;
    float acc = 0.0f;
    for (int ch = 0; ch < 2; ++ch) {
        for (int k = tid; k < 25 * SZ; k += 1024) {
            s_sino[k] = g_filt[(b * NA + ch * 25) * SZ + k];
        }
        __syncthreads();
        #pragma unroll 5
        for (int al = 0; al < 25; ++al) {
            int a = ch * 25 + al;
            float det = xx * s_cos[a] + yy * s_sin[a] + CEN;
            float df = floorf(det);
            int i0 = (int)df;
            i0 = i0 < 0 ? 0 : (i0 > SZ - 2 ? SZ - 2 : i0);
            float w = det - (float)i0;
            float v = s_sino[al * SZ + i0] * (1.0f - w) + s_sino[al * SZ + i0 + 1] * w;
            if (det >= 0.0f && det <= (float)(SZ - 1)) acc += v;
        }
        __syncthreads();
    }
    float m = (xx*xx + yy*yy <= 16384.0f) ? 1.0f : 0.0f;
    int o = b * SS + i * SZ + j;
    out_up[o] = yprev[o] + step[0] * (acc * m);
}

// ---------------- 4. conv1: 2 -> 32 tiled f32x2 (proven) -------------------
#define RW 36
__global__ void __launch_bounds__(256) k_conv1(const float* __restrict__ yup,
                                               const float* __restrict__ ycat,
                                               const float* __restrict__ w1,
                                               const float* __restrict__ b1) {
    __shared__ __align__(16) float s_w2[18 * 32];
    __shared__ float s_b[NC];
    __shared__ __align__(16) float s_in0[10 * RW];
    __shared__ __align__(16) float s_in1[10 * RW];
    int tid = threadIdx.x;
    int b = blockIdx.z;
    int gx0 = blockIdx.x * 32 - 1;
    int gy0 = blockIdx.y * 8 - 1;
    for (int idx = tid; idx < 18 * 32; idx += 256) {
        int kk = idx >> 5, oc = idx & 31;
        s_w2[idx] = w1[oc * 18 + kk];
    }
    if (tid < NC) s_b[tid] = b1[tid];
    for (int idx = tid; idx < 10 * RW; idx += 256) {
        int rr = idx / RW, ccx = idx % RW;
        int gy = gy0 + rr, gx = gx0 + ccx;
        bool ok = (ccx < 34) && (gy >= 0) && (gy < SZ) && (gx >= 0) && (gx < SZ);
        int gi = b * SS + gy * SZ + gx;
        s_in0[idx] = ok ? yup[gi]  : 0.0f;
        s_in1[idx] = ok ? ycat[gi] : 0.0f;
    }
    __syncthreads();

    int q = tid & 7, r = (tid >> 3) & 7, og = tid >> 6;
    u64 acc2[4][4];
    #pragma unroll
    for (int op = 0; op < 4; ++op) {
        int oc0 = og * 8 + 2 * op;
        u64 bp = pk2(s_b[oc0], s_b[oc0 + 1]);
        #pragma unroll
        for (int p = 0; p < 4; ++p) acc2[op][p] = bp;
    }
    #pragma unroll
    for (int ic = 0; ic < 2; ++ic) {
        const float* inb = ic ? s_in1 : s_in0;
        const float* wb  = &s_w2[ic * 288];
        #pragma unroll
        for (int ky = 0; ky < 3; ++ky) {
            const float* rowp = inb + (r + ky) * RW + q * 4;
            float4 va = *(const float4*)rowp;
            float2 vb = *(const float2*)(rowp + 4);
            float ivf[6] = {va.x, va.y, va.z, va.w, vb.x, vb.y};
            u64 ivp[6];
            #pragma unroll
            for (int m = 0; m < 6; ++m) ivp[m] = pk2(ivf[m], ivf[m]);
            #pragma unroll
            for (int kx = 0; kx < 3; ++kx) {
                const ulonglong2 wv0 = *(const ulonglong2*)&wb[(ky*3+kx)*32 + og*8];
                const ulonglong2 wv1 = *(const ulonglong2*)&wb[(ky*3+kx)*32 + og*8 + 4];
                u64 wp[4] = {wv0.x, wv0.y, wv1.x, wv1.y};
                #pragma unroll
                for (int op = 0; op < 4; ++op)
                    #pragma unroll
                    for (int p = 0; p < 4; ++p)
                        acc2[op][p] = fma2(wp[op], ivp[kx + p], acc2[op][p]);
            }
        }
    }
    int gy = blockIdx.y * 8 + r;
    int gxb = blockIdx.x * 32 + q * 4;
    #pragma unroll
    for (int op = 0; op < 4; ++op) {
        int oc0 = og * 8 + 2 * op;
        float l0,h0,l1,h1,l2,h2,l3,h3;
        unpk2(acc2[op][0], l0, h0); unpk2(acc2[op][1], l1, h1);
        unpk2(acc2[op][2], l2, h2); unpk2(acc2[op][3], l3, h3);
        float4 vlo = make_float4(fmaxf(l0,0.f), fmaxf(l1,0.f), fmaxf(l2,0.f), fmaxf(l3,0.f));
        float4 vhi = make_float4(fmaxf(h0,0.f), fmaxf(h1,0.f), fmaxf(h2,0.f), fmaxf(h3,0.f));
        *(float4*)&g_h1[((b * NC + oc0)     << 16) + gy * SZ + gxb] = vlo;
        *(float4*)&g_h1[((b * NC + oc0 + 1) << 16) + gy * SZ + gxb] = vhi;
    }
}

// ---------------- 5. conv2: 32 -> 32 f32x2 (R8 proven config) --------------
#define ICH 16
__global__ void __launch_bounds__(256) k_conv2(const float* __restrict__ w2,
                                               const float* __restrict__ b2) {
    __shared__ __align__(16) float s_w[ICH * 9 * 32];   // [ic][k][oc]
    __shared__ __align__(16) float s_in[ICH * 10 * RW]; // [ic][row][col]
    __shared__ float s_b[NC];
    int tid = threadIdx.x;
    int q = tid & 7, r = (tid >> 3) & 7, og = tid >> 6;
    int b = blockIdx.z;
    int gx0 = blockIdx.x * 32 - 1;
    int gy0 = blockIdx.y * 8 - 1;
    if (tid < NC) s_b[tid] = b2[tid];

    u64 acc2[4][4];
    #pragma unroll
    for (int op = 0; op < 4; ++op)
        #pragma unroll
        for (int p = 0; p < 4; ++p) acc2[op][p] = 0ULL;

    for (int cc = 0; cc < 2; ++cc) {
        int icb = cc * ICH;
        __syncthreads();
        for (int idx = tid; idx < ICH * 288; idx += 256) {
            int ic = idx / 288, rem = idx % 288;
            int k = rem >> 5, oc = rem & 31;
            s_w[idx] = w2[oc * 288 + (icb + ic) * 9 + k];
        }
        for (int idx = tid; idx < ICH * 10 * RW; idx += 256) {
            int ic = idx / (10 * RW), rem = idx % (10 * RW);
            int rr = rem / RW, ccx = rem % RW;
            int gy = gy0 + rr, gx = gx0 + ccx;
            bool ok = (ccx < 34) && (gy >= 0) && (gy < SZ) && (gx >= 0) && (gx < SZ);
            s_in[idx] = ok ? g_h1[((b * NC + icb + ic) << 16) + gy * SZ + gx] : 0.0f;
        }
        __syncthreads();

        for (int ic = 0; ic < ICH; ++ic) {
            const float* inb = &s_in[ic * 10 * RW];
            const float* wb  = &s_w[ic * 288];
            #pragma unroll
            for (int ky = 0; ky < 3; ++ky) {
                const float* rowp = inb + (r + ky) * RW + q * 4;
                float4 va = *(const float4*)rowp;
                float2 vb = *(const float2*)(rowp + 4);
                float ivf[6] = {va.x, va.y, va.z, va.w, vb.x, vb.y};
                u64 ivp[6];
                #pragma unroll
                for (int m = 0; m < 6; ++m) ivp[m] = pk2(ivf[m], ivf[m]);
                #pragma unroll
                for (int kx = 0; kx < 3; ++kx) {
                    const ulonglong2 wv0 = *(const ulonglong2*)&wb[(ky*3+kx)*32 + og*8];
                    const ulonglong2 wv1 = *(const ulonglong2*)&wb[(ky*3+kx)*32 + og*8 + 4];
                    u64 wp[4] = {wv0.x, wv0.y, wv1.x, wv1.y};
                    #pragma unroll
                    for (int op = 0; op < 4; ++op)
                        #pragma unroll
                        for (int p = 0; p < 4; ++p)
                            acc2[op][p] = fma2(wp[op], ivp[kx + p], acc2[op][p]);
                }
            }
        }
    }
    int gy = blockIdx.y * 8 + r;
    int gxb = blockIdx.x * 32 + q * 4;
    #pragma unroll
    for (int op = 0; op < 4; ++op) {
        int oc0 = og * 8 + 2 * op;
        float blo = s_b[oc0], bhi = s_b[oc0 + 1];
        float l0,h0,l1,h1,l2,h2,l3,h3;
        unpk2(acc2[op][0], l0, h0); unpk2(acc2[op][1], l1, h1);
        unpk2(acc2[op][2], l2, h2); unpk2(acc2[op][3], l3, h3);
        float4 vlo = make_float4(fmaxf(l0+blo,0.f), fmaxf(l1+blo,0.f),
                                 fmaxf(l2+blo,0.f), fmaxf(l3+blo,0.f));
        float4 vhi = make_float4(fmaxf(h0+bhi,0.f), fmaxf(h1+bhi,0.f),
                                 fmaxf(h2+bhi,0.f), fmaxf(h3+bhi,0.f));
        *(float4*)&g_h2[((b * NC + oc0)     << 16) + gy * SZ + gxb] = vlo;
        *(float4*)&g_h2[((b * NC + oc0 + 1) << 16) + gy * SZ + gxb] = vhi;
    }
}

// ---------------- 6. conv3: 32 -> 1, smem-chunked (proven) -----------------
__global__ void __launch_bounds__(256) k_conv3(const float* __restrict__ w3,
                                               const float* __restrict__ b3,
                                               float* __restrict__ out_img) {
    __shared__ float s_w[NC * 9];
    __shared__ __align__(16) float s_in[8 * 10 * RW];
    int tid = threadIdx.x;
    int b = blockIdx.z;
    int gx0 = blockIdx.x * 32 - 1;
    int gy0 = blockIdx.y * 8 - 1;
    for (int k = tid; k < NC * 9; k += 256) s_w[k] = w3[k];

    int jl = tid & 31, il = tid >> 5;
    float acc = b3[0];
    for (int cc = 0; cc < 4; ++cc) {
        __syncthreads();
        for (int idx = tid; idx < 8 * 10 * RW; idx += 256) {
            int ic = idx / (10 * RW), rem = idx % (10 * RW);
            int rr = rem / RW, ccx = rem % RW;
            int gy = gy0 + rr, gx = gx0 + ccx;
            bool ok = (ccx < 34) && (gy >= 0) && (gy < SZ) && (gx >= 0) && (gx < SZ);
            s_in[idx] = ok ? g_h2[((b * NC + cc * 8 + ic) << 16) + gy * SZ + gx] : 0.0f;
        }
        __syncthreads();
        #pragma unroll
        for (int ic = 0; ic < 8; ++ic) {
            const float* inb = &s_in[ic * 10 * RW];
            const float* w = &s_w[(cc * 8 + ic) * 9];
            #pragma unroll
            for (int ky = 0; ky < 3; ++ky) {
                const float* rowp = inb + (il + ky) * RW + jl;
                acc += rowp[0] * w[ky*3] + rowp[1] * w[ky*3+1] + rowp[2] * w[ky*3+2];
            }
        }
    }
    int gy = blockIdx.y * 8 + il;
    int gx = blockIdx.x * 32 + jl;
    out_img[b * SS + gy * SZ + gx] = acc;
}

// ---------------- launch ----------------
extern "C" void kernel_launch(void* const* d_in, const int* in_sizes, int n_in,
                              void* d_out, int out_size) {
    const float *x_sino = 0, *y_prev = 0, *y_cat = 0, *angles = 0, *step = 0;
    const float *w1 = 0, *b1 = 0, *w2 = 0, *b2 = 0, *w3 = 0, *b3 = 0;

    int ix = -1;
    for (int i = 0; i < n_in; ++i) if (in_sizes[i] == 51200) ix = i;
    bool dict_order = (ix == 0);

    int n262 = 0, n32 = 0, n1 = 0;
    for (int i = 0; i < n_in; ++i) {
        const float* p = (const float*)d_in[i];
        switch (in_sizes[i]) {
            case 51200: x_sino = p; break;
            case 50:    angles = p; break;
            case 576:   w1 = p; break;
            case 9216:  w2 = p; break;
            case 288:   w3 = p; break;
            case 262144:
                if (dict_order) { if (n262 == 0) y_prev = p; else y_cat = p; }
                else            { if (n262 == 0) y_cat  = p; else y_prev = p; }
                ++n262; break;
            case 32:
                if (n32 == 0) b1 = p; else b2 = p;
                ++n32; break;
            case 1:
                if (dict_order) { if (n1 == 0) step = p; else b3 = p; }
                else            { if (n1 == 0) b3   = p; else step = p; }
                ++n1; break;
            default: break;
        }
    }

    float* out_img = (float*)d_out;
    float* out_up;
    if (out_size >= 2 * BB * SS) {
        out_up = (float*)d_out + BB * SS;
    } else {
        cudaGetSymbolAddress((void**)&out_up, g_up);
    }

    k_radon<<<dim3(NA, BB, NZ), 256>>>(y_prev, angles);
    k_filter<<<dim3(NA, BB), 256>>>(x_sino);
    k_backproj<<<dim3(SZ / 4, BB), 1024>>>(y_prev, angles, step, out_up);
    k_conv1<<<dim3(8, 32, BB), 256>>>(out_up, y_cat, w1, b1);
    k_conv2<<<dim3(8, 32, BB), 256>>>(w2, b2);
    k_conv3<<<dim3(8, 32, BB), 256>>>(w3, b3, out_img);
}